// round 6
// baseline (speedup 1.0000x reference)
#include <cuda_runtime.h>
#include <cstdint>
#include <math.h>

// ---------------------------------------------------------------------------
// WaveNet B=4 T=32768 RC=120 SC=240 NB=16 NC=256.
// R3 (second resubmit after infra timeouts): f32x2 register-tiled GEMMs +
// cp.async triple-buffered weight pipeline, in-register gated activation
// (outputs o and o+120 in same thread), fast exp-based tanh/sigmoid. One
// fused kernel per residual block.
// ---------------------------------------------------------------------------

#define T_LEN   32768
#define BN      4
#define RC_     120
#define C2_     240
#define NM_     80
#define XC_     320
#define O2_     360
#define SC_     240
#define NB_     16
#define NC_     256
#define TT_     64
#define NTHR    512

// ---- device-global scratch ----
__device__ __align__(16) float g_res[2][BN * RC_ * T_LEN];
__device__ __align__(16) float g_skip[BN * SC_ * T_LEN];
__device__ __align__(16) float g_w1[NB_ * XC_ * C2_];   // [i][c<320][o<240]
__device__ __align__(16) float g_w2[NB_ * RC_ * O2_];   // [i][c<120][o<360]
__device__ __align__(16) float g_w3[SC_ * NC_];         // [c<240][o<256]
__device__ __align__(16) float g_w4[NC_ * NC_];         // [c<256][o<256]

// ---- f32x2 helpers ----
__device__ __forceinline__ void fma2(unsigned long long& d,
                                     unsigned long long a,
                                     unsigned long long b) {
    asm("fma.rn.f32x2 %0, %1, %2, %3;" : "=l"(d) : "l"(a), "l"(b), "l"(d));
}
__device__ __forceinline__ unsigned long long pack2(float x, float y) {
    unsigned long long r;
    asm("mov.b64 %0, {%1, %2};" : "=l"(r) : "f"(x), "f"(y));
    return r;
}
__device__ __forceinline__ float2 unpack2(unsigned long long v) {
    float2 f;
    asm("mov.b64 {%0, %1}, %2;" : "=f"(f.x), "=f"(f.y) : "l"(v));
    return f;
}

// ---- cp.async helpers ----
__device__ __forceinline__ void cp16(uint32_t dst, const void* src) {
    asm volatile("cp.async.cg.shared.global [%0], [%1], 16;"
                 :: "r"(dst), "l"(src) : "memory");
}
__device__ __forceinline__ void cp_commit() {
    asm volatile("cp.async.commit_group;" ::: "memory");
}
template <int N>
__device__ __forceinline__ void cp_wait() {
    asm volatile("cp.async.wait_group %0;" :: "n"(N) : "memory");
}

// ---- fast activations (ex2/rcp.approx based; rel err ~1e-6) ----
__device__ __forceinline__ float fast_tanh(float x) {
    float e = __expf(2.0f * x);
    return 1.0f - __fdividef(2.0f, e + 1.0f);
}
__device__ __forceinline__ float fast_sig(float x) {
    return __fdividef(1.0f, 1.0f + __expf(-x));
}

// ---------------------------------------------------------------------------
__global__ void prep_kernel(const float* __restrict__ cond_w,
                            const float* __restrict__ dil_w,
                            const float* __restrict__ skip_w,
                            const float* __restrict__ res_w,
                            const float* __restrict__ out_w,
                            const float* __restrict__ end_w) {
    const int stride = gridDim.x * blockDim.x;
    const int t0 = blockIdx.x * blockDim.x + threadIdx.x;

    for (int idx = t0; idx < NB_ * XC_ * C2_; idx += stride) {
        int i = idx / (XC_ * C2_);
        int r = idx % (XC_ * C2_);
        int c = r / C2_;
        int o = r % C2_;
        float w;
        if (c < RC_)          w = dil_w[((i * C2_ + o) * RC_ + c) * 2 + 0];
        else if (c < 2 * RC_) w = dil_w[((i * C2_ + o) * RC_ + (c - RC_)) * 2 + 1];
        else                  w = cond_w[(i * C2_ + o) * NM_ + (c - 2 * RC_)];
        g_w1[idx] = w;
    }
    for (int idx = t0; idx < NB_ * RC_ * O2_; idx += stride) {
        int i = idx / (RC_ * O2_);
        int r = idx % (RC_ * O2_);
        int c = r / O2_;
        int o = r % O2_;
        g_w2[idx] = (o < SC_) ? skip_w[(i * SC_ + o) * RC_ + c]
                              : res_w[(i * RC_ + (o - SC_)) * RC_ + c];
    }
    for (int idx = t0; idx < SC_ * NC_; idx += stride) {
        int c = idx / NC_;
        int o = idx % NC_;
        g_w3[idx] = out_w[o * SC_ + c];
    }
    for (int idx = t0; idx < NC_ * NC_; idx += stride) {
        int c = idx / NC_;
        int o = idx % NC_;
        g_w4[idx] = end_w[o * NC_ + c];
    }
}

__global__ void init_kernel(const float* __restrict__ wav,
                            const float* __restrict__ wav_w,
                            const float* __restrict__ wav_b) {
    const int stride = gridDim.x * blockDim.x;
    const int t0 = blockIdx.x * blockDim.x + threadIdx.x;
    for (int idx = t0; idx < BN * RC_ * T_LEN; idx += stride) {
        int b = idx / (RC_ * T_LEN);
        int r = idx % (RC_ * T_LEN);
        int c = r >> 15;
        int t = r & (T_LEN - 1);
        g_res[0][idx] = wav_w[c] * wav[b * T_LEN + t] + wav_b[c];
    }
    for (int idx = t0; idx < BN * SC_ * T_LEN; idx += stride)
        g_skip[idx] = 0.0f;
}

// ---------------------------------------------------------------------------
// Fused residual block. SMEM (floats):
//   xs   [0, 20480)        : X tile 320 rows x 64 t            (phase 1)
//   wb_k [20480 + k*9600)  : 3 weight buffers, 40x240 each     (phase 1)
//   w2   [0, 43200)        : full W2 120x360                   (phase 2)
//   act  [43200, 50880)    : 120 x 64                          (phase 2)
// total 50880 floats = 203520 B
// ---------------------------------------------------------------------------
#define XS_F    0
#define WB_F    20480
#define WCHUNK  9600        // 40 rows * 240
#define W2_F    0
#define ACT_F   43200

__global__ __launch_bounds__(NTHR, 1) void block_kernel(
    int blk, int d, int pp,
    const float* __restrict__ cond,
    const float* __restrict__ dil_b, const float* __restrict__ cond_b,
    const float* __restrict__ skip_b, const float* __restrict__ res_b) {
    extern __shared__ float sm[];
    const uint32_t smb = (uint32_t)__cvta_generic_to_shared(sm);

    const int tid = threadIdx.x;
    const int b   = blockIdx.y;
    const int t0  = blockIdx.x * TT_;

    const float* resin  = g_res[pp] + b * RC_ * T_LEN;
    float*       resout = g_res[pp ^ 1] + b * RC_ * T_LEN;
    const float* condb  = cond + b * NM_ * T_LEN;
    const float* w1base = g_w1 + blk * XC_ * C2_;

    // ---- prologue: cp.async W1 chunks 0,1 ----
#pragma unroll 1
    for (int ch = 0; ch < 2; ch++) {
        const float* src = w1base + ch * WCHUNK;
        uint32_t dst = smb + (WB_F + ch * WCHUNK) * 4;
        for (int i = tid; i < WCHUNK / 4; i += NTHR)
            cp16(dst + i * 16, src + i * 4);
        cp_commit();
    }

    // ---- stage X tile ----
    // rows 120..319 (current res + cond): vectorized
    float* xs = sm + XS_F;
    for (int idx = tid; idx < 200 * 16; idx += NTHR) {
        int rr = idx >> 4;          // 0..199
        int c4 = idx & 15;
        const float* src = (rr < RC_) ? (resin + (rr << 15))
                                      : (condb + ((rr - RC_) << 15));
        float4 v = *(const float4*)(src + t0 + c4 * 4);
        *(float4*)(xs + ((120 + rr) << 6) + c4 * 4) = v;
    }
    // rows 0..119 (shifted): scalar with boundary
    for (int idx = tid; idx < RC_ * TT_; idx += NTHR) {
        int r = idx >> 6;
        int t = idx & 63;
        int tt = t0 + t - d;
        xs[(r << 6) + t] = (tt >= 0) ? resin[(r << 15) + tt] : 0.0f;
    }

    const int og = tid >> 4;       // 0..31 (30 active)
    const int tg = tid & 15;       // 4 t each
    const bool active = (og < 30);

    // ---- GEMM1: thread owns outputs {og*4..+3} and {og*4+120..+123} ----
    unsigned long long acc[4][4];
    if (active) {
#pragma unroll
        for (int p = 0; p < 4; p++) {
            int o = og * 4 + (p & 1) * 2 + (p >> 1) * RC_;
            float b0 = dil_b[blk * C2_ + o]     + cond_b[blk * C2_ + o];
            float b1 = dil_b[blk * C2_ + o + 1] + cond_b[blk * C2_ + o + 1];
            unsigned long long bv = pack2(b0, b1);
#pragma unroll
            for (int j = 0; j < 4; j++) acc[p][j] = bv;
        }
    }

    // pipeline: 8 chunks of 40 K-rows, 3 buffers, 1 sync/chunk
#pragma unroll 1
    for (int ch = 0; ch < 8; ch++) {
        if (ch == 7) cp_wait<0>(); else cp_wait<1>();
        __syncthreads();
        if (ch + 2 < 8) {
            const float* src = w1base + (ch + 2) * WCHUNK;
            uint32_t dst = smb + (WB_F + ((ch + 2) % 3) * WCHUNK) * 4;
            for (int i = tid; i < WCHUNK / 4; i += NTHR)
                cp16(dst + i * 16, src + i * 4);
            cp_commit();
        }
        if (active) {
            const float* wb = sm + WB_F + (ch % 3) * WCHUNK;
            const float* xrow = xs + ((ch * 40) << 6) + (tg << 2);
#pragma unroll 5
            for (int cc = 0; cc < 40; cc++) {
                float4 xv = *(const float4*)(xrow + (cc << 6));
                unsigned long long xx0 = pack2(xv.x, xv.x);
                unsigned long long xx1 = pack2(xv.y, xv.y);
                unsigned long long xx2 = pack2(xv.z, xv.z);
                unsigned long long xx3 = pack2(xv.w, xv.w);
                ulonglong2 wA = *(const ulonglong2*)(wb + cc * C2_ + (og << 2));
                ulonglong2 wB = *(const ulonglong2*)(wb + cc * C2_ + RC_ + (og << 2));
                fma2(acc[0][0], wA.x, xx0); fma2(acc[0][1], wA.x, xx1);
                fma2(acc[0][2], wA.x, xx2); fma2(acc[0][3], wA.x, xx3);
                fma2(acc[1][0], wA.y, xx0); fma2(acc[1][1], wA.y, xx1);
                fma2(acc[1][2], wA.y, xx2); fma2(acc[1][3], wA.y, xx3);
                fma2(acc[2][0], wB.x, xx0); fma2(acc[2][1], wB.x, xx1);
                fma2(acc[2][2], wB.x, xx2); fma2(acc[2][3], wB.x, xx3);
                fma2(acc[3][0], wB.y, xx0); fma2(acc[3][1], wB.y, xx1);
                fma2(acc[3][2], wB.y, xx2); fma2(acc[3][3], wB.y, xx3);
            }
        }
    }
    __syncthreads();   // xs + all weight buffers now dead

    // ---- prefetch ALL of W2 (overlaps activation compute) ----
    {
        const float* src = g_w2 + blk * RC_ * O2_;
        uint32_t dst = smb + W2_F * 4;
        for (int i = tid; i < RC_ * O2_ / 4; i += NTHR)
            cp16(dst + i * 16, src + i * 4);
        cp_commit();
    }

    // ---- gated activation entirely in registers ----
    float* act = sm + ACT_F;
    if (active) {
        float a0[4], a1[4], a2[4], a3[4];
#pragma unroll
        for (int j = 0; j < 4; j++) {
            float2 gA = unpack2(acc[0][j]);
            float2 gB = unpack2(acc[1][j]);
            float2 sA = unpack2(acc[2][j]);
            float2 sB = unpack2(acc[3][j]);
            a0[j] = fast_tanh(gA.x) * fast_sig(sA.x);
            a1[j] = fast_tanh(gA.y) * fast_sig(sA.y);
            a2[j] = fast_tanh(gB.x) * fast_sig(sB.x);
            a3[j] = fast_tanh(gB.y) * fast_sig(sB.y);
        }
        int r0 = og * 4;
        *(float4*)(act + ((r0 + 0) << 6) + (tg << 2)) = make_float4(a0[0], a0[1], a0[2], a0[3]);
        *(float4*)(act + ((r0 + 1) << 6) + (tg << 2)) = make_float4(a1[0], a1[1], a1[2], a1[3]);
        *(float4*)(act + ((r0 + 2) << 6) + (tg << 2)) = make_float4(a2[0], a2[1], a2[2], a2[3]);
        *(float4*)(act + ((r0 + 3) << 6) + (tg << 2)) = make_float4(a3[0], a3[1], a3[2], a3[3]);
    }
    cp_wait<0>();
    __syncthreads();   // act + W2 visible

    // ---- GEMM2: 360 outs x 64 t, K=120, W2 fully resident ----
    unsigned long long acc2[6][4];
    if (active) {
#pragma unroll
        for (int q = 0; q < 6; q++) {
            int o = og * 12 + q * 2;
            float b0 = (o < SC_)     ? skip_b[blk * SC_ + o]     : res_b[blk * RC_ + o - SC_];
            float b1 = (o + 1 < SC_) ? skip_b[blk * SC_ + o + 1] : res_b[blk * RC_ + o + 1 - SC_];
            unsigned long long bv = pack2(b0, b1);
#pragma unroll
            for (int j = 0; j < 4; j++) acc2[q][j] = bv;
        }
        const float* w2 = sm + W2_F;
        const float* arow = act + (tg << 2);
#pragma unroll 4
        for (int cc = 0; cc < RC_; cc++) {
            float4 xv = *(const float4*)(arow + (cc << 6));
            unsigned long long xx0 = pack2(xv.x, xv.x);
            unsigned long long xx1 = pack2(xv.y, xv.y);
            unsigned long long xx2 = pack2(xv.z, xv.z);
            unsigned long long xx3 = pack2(xv.w, xv.w);
            const ulonglong2* wrow = (const ulonglong2*)(w2 + cc * O2_ + og * 12);
            ulonglong2 wA = wrow[0];
            ulonglong2 wB = wrow[1];
            ulonglong2 wC = wrow[2];
            fma2(acc2[0][0], wA.x, xx0); fma2(acc2[0][1], wA.x, xx1);
            fma2(acc2[0][2], wA.x, xx2); fma2(acc2[0][3], wA.x, xx3);
            fma2(acc2[1][0], wA.y, xx0); fma2(acc2[1][1], wA.y, xx1);
            fma2(acc2[1][2], wA.y, xx2); fma2(acc2[1][3], wA.y, xx3);
            fma2(acc2[2][0], wB.x, xx0); fma2(acc2[2][1], wB.x, xx1);
            fma2(acc2[2][2], wB.x, xx2); fma2(acc2[2][3], wB.x, xx3);
            fma2(acc2[3][0], wB.y, xx0); fma2(acc2[3][1], wB.y, xx1);
            fma2(acc2[3][2], wB.y, xx2); fma2(acc2[3][3], wB.y, xx3);
            fma2(acc2[4][0], wC.x, xx0); fma2(acc2[4][1], wC.x, xx1);
            fma2(acc2[4][2], wC.x, xx2); fma2(acc2[4][3], wC.x, xx3);
            fma2(acc2[5][0], wC.y, xx0); fma2(acc2[5][1], wC.y, xx1);
            fma2(acc2[5][2], wC.y, xx2); fma2(acc2[5][3], wC.y, xx3);
        }

        // ---- epilogue ----
        const int t = t0 + (tg << 2);
        float* skipb = g_skip + b * SC_ * T_LEN;
#pragma unroll
        for (int q = 0; q < 6; q++) {
            float2 v0 = unpack2(acc2[q][0]);
            float2 v1 = unpack2(acc2[q][1]);
            float2 v2 = unpack2(acc2[q][2]);
            float2 v3 = unpack2(acc2[q][3]);
            int o = og * 12 + q * 2;
            if (o < SC_) {
                float4* p0 = (float4*)(skipb + (o << 15) + t);
                float4* p1 = (float4*)(skipb + ((o + 1) << 15) + t);
                float4 c0 = *p0, c1 = *p1;
                c0.x += v0.x; c0.y += v1.x; c0.z += v2.x; c0.w += v3.x;
                c1.x += v0.y; c1.y += v1.y; c1.z += v2.y; c1.w += v3.y;
                *p0 = c0; *p1 = c1;
            } else {
                int r = o - SC_;
                float4 r0 = *(const float4*)(resin + (r << 15) + t);
                float4 r1 = *(const float4*)(resin + ((r + 1) << 15) + t);
                r0.x += v0.x; r0.y += v1.x; r0.z += v2.x; r0.w += v3.x;
                r1.x += v0.y; r1.y += v1.y; r1.z += v2.y; r1.w += v3.y;
                *(float4*)(resout + (r << 15) + t) = r0;
                *(float4*)(resout + ((r + 1) << 15) + t) = r1;
            }
        }
    }
}

// ---------------------------------------------------------------------------
// Head. SMEM (floats):
//   xsF  [0, 15360)          : relu(skip) 240 x 64            (phase A)
//   a_k  [15360 + k*12288)   : 3 bufs, 48x256 w3 chunks       (phase A)
//   oact [0, 16384)          : relu(o) 256 x 64               (phase B)
//   c_k  [16384 + k*16384)   : 2 bufs, 64x256 w4 chunks       (phase B)
// total 52224 floats = 208896 B
// ---------------------------------------------------------------------------
#define XSF_F   0
#define AB_F    15360
#define ACH     12288       // 48 rows * 256
#define OACT_F  0
#define CB_F    16384
#define CCH     16384       // 64 rows * 256

__global__ __launch_bounds__(NTHR, 1) void final_kernel(
    float* __restrict__ out,
    const float* __restrict__ out_b,
    const float* __restrict__ end_b) {
    extern __shared__ float sm[];
    const uint32_t smb = (uint32_t)__cvta_generic_to_shared(sm);

    const int tid = threadIdx.x;
    const int b   = blockIdx.y;
    const int t0  = blockIdx.x * TT_;

    // prologue: w3 chunks 0,1
#pragma unroll 1
    for (int ch = 0; ch < 2; ch++) {
        const float* src = g_w3 + ch * ACH;
        uint32_t dst = smb + (AB_F + ch * ACH) * 4;
        for (int i = tid; i < ACH / 4; i += NTHR)
            cp16(dst + i * 16, src + i * 4);
        cp_commit();
    }

    // stage relu(skip)
    float* xs = sm + XSF_F;
    const float* skipb = g_skip + b * SC_ * T_LEN;
    for (int idx = tid; idx < SC_ * 16; idx += NTHR) {
        int r = idx >> 4;
        int c4 = idx & 15;
        float4 v = *(const float4*)(skipb + (r << 15) + t0 + c4 * 4);
        v.x = fmaxf(v.x, 0.f); v.y = fmaxf(v.y, 0.f);
        v.z = fmaxf(v.z, 0.f); v.w = fmaxf(v.w, 0.f);
        *(float4*)(xs + (r << 6) + c4 * 4) = v;
    }

    const int og = tid >> 4;    // 0..31
    const int tg = tid & 15;

    // ---- GEMM A: 256 outs, K=240, 5 chunks of 48, 3 buffers ----
    unsigned long long acc[4][4];
#pragma unroll
    for (int p = 0; p < 4; p++) {
        int o = og * 8 + p * 2;
        unsigned long long bv = pack2(out_b[o], out_b[o + 1]);
#pragma unroll
        for (int j = 0; j < 4; j++) acc[p][j] = bv;
    }
#pragma unroll 1
    for (int ch = 0; ch < 5; ch++) {
        if (ch == 4) cp_wait<0>(); else cp_wait<1>();
        __syncthreads();
        if (ch + 2 < 5) {
            const float* src = g_w3 + (ch + 2) * ACH;
            uint32_t dst = smb + (AB_F + ((ch + 2) % 3) * ACH) * 4;
            for (int i = tid; i < ACH / 4; i += NTHR)
                cp16(dst + i * 16, src + i * 4);
            cp_commit();
        }
        const float* wb = sm + AB_F + (ch % 3) * ACH;
        const float* xrow = xs + ((ch * 48) << 6) + (tg << 2);
#pragma unroll 4
        for (int cc = 0; cc < 48; cc++) {
            float4 xv = *(const float4*)(xrow + (cc << 6));
            unsigned long long xx0 = pack2(xv.x, xv.x);
            unsigned long long xx1 = pack2(xv.y, xv.y);
            unsigned long long xx2 = pack2(xv.z, xv.z);
            unsigned long long xx3 = pack2(xv.w, xv.w);
            const ulonglong2* wrow = (const ulonglong2*)(wb + cc * NC_ + og * 8);
            ulonglong2 wA = wrow[0];
            ulonglong2 wB = wrow[1];
            fma2(acc[0][0], wA.x, xx0); fma2(acc[0][1], wA.x, xx1);
            fma2(acc[0][2], wA.x, xx2); fma2(acc[0][3], wA.x, xx3);
            fma2(acc[1][0], wA.y, xx0); fma2(acc[1][1], wA.y, xx1);
            fma2(acc[1][2], wA.y, xx2); fma2(acc[1][3], wA.y, xx3);
            fma2(acc[2][0], wB.x, xx0); fma2(acc[2][1], wB.x, xx1);
            fma2(acc[2][2], wB.x, xx2); fma2(acc[2][3], wB.x, xx3);
            fma2(acc[3][0], wB.y, xx0); fma2(acc[3][1], wB.y, xx1);
            fma2(acc[3][2], wB.y, xx2); fma2(acc[3][3], wB.y, xx3);
        }
    }
    __syncthreads();    // xs + a-buffers dead

    // prefetch w4 chunks 0,1 (overlaps relu/oact writes)
#pragma unroll 1
    for (int ch = 0; ch < 2; ch++) {
        const float* src = g_w4 + ch * CCH;
        uint32_t dst = smb + (CB_F + ch * CCH) * 4;
        for (int i = tid; i < CCH / 4; i += NTHR)
            cp16(dst + i * 16, src + i * 4);
        cp_commit();
    }

    // relu -> oact
    float* oact = sm + OACT_F;
#pragma unroll
    for (int p = 0; p < 4; p++) {
        float2 v0 = unpack2(acc[p][0]);
        float2 v1 = unpack2(acc[p][1]);
        float2 v2 = unpack2(acc[p][2]);
        float2 v3 = unpack2(acc[p][3]);
        int o = og * 8 + p * 2;
        *(float4*)(oact + (o << 6) + (tg << 2)) =
            make_float4(fmaxf(v0.x, 0.f), fmaxf(v1.x, 0.f), fmaxf(v2.x, 0.f), fmaxf(v3.x, 0.f));
        *(float4*)(oact + ((o + 1) << 6) + (tg << 2)) =
            make_float4(fmaxf(v0.y, 0.f), fmaxf(v1.y, 0.f), fmaxf(v2.y, 0.f), fmaxf(v3.y, 0.f));
    }

    // ---- GEMM B: 256 outs, K=256, 4 chunks of 64, 2 buffers ----
    unsigned long long acc2[4][4];
#pragma unroll
    for (int p = 0; p < 4; p++) {
        int o = og * 8 + p * 2;
        unsigned long long bv = pack2(end_b[o], end_b[o + 1]);
#pragma unroll
        for (int j = 0; j < 4; j++) acc2[p][j] = bv;
    }
#pragma unroll 1
    for (int ch = 0; ch < 4; ch++) {
        if (ch == 3) cp_wait<0>(); else cp_wait<1>();
        __syncthreads();        // chunk data + (iter0) oact visible
        const float* wb = sm + CB_F + (ch % 2) * CCH;
        const float* xrow = oact + ((ch * 64) << 6) + (tg << 2);
#pragma unroll 4
        for (int cc = 0; cc < 64; cc++) {
            float4 xv = *(const float4*)(xrow + (cc << 6));
            unsigned long long xx0 = pack2(xv.x, xv.x);
            unsigned long long xx1 = pack2(xv.y, xv.y);
            unsigned long long xx2 = pack2(xv.z, xv.z);
            unsigned long long xx3 = pack2(xv.w, xv.w);
            const ulonglong2* wrow = (const ulonglong2*)(wb + cc * NC_ + og * 8);
            ulonglong2 wA = wrow[0];
            ulonglong2 wB = wrow[1];
            fma2(acc2[0][0], wA.x, xx0); fma2(acc2[0][1], wA.x, xx1);
            fma2(acc2[0][2], wA.x, xx2); fma2(acc2[0][3], wA.x, xx3);
            fma2(acc2[1][0], wA.y, xx0); fma2(acc2[1][1], wA.y, xx1);
            fma2(acc2[1][2], wA.y, xx2); fma2(acc2[1][3], wA.y, xx3);
            fma2(acc2[2][0], wB.x, xx0); fma2(acc2[2][1], wB.x, xx1);
            fma2(acc2[2][2], wB.x, xx2); fma2(acc2[2][3], wB.x, xx3);
            fma2(acc2[3][0], wB.y, xx0); fma2(acc2[3][1], wB.y, xx1);
            fma2(acc2[3][2], wB.y, xx2); fma2(acc2[3][3], wB.y, xx3);
        }
        __syncthreads();        // done reading buf ch%2
        if (ch + 2 < 4) {
            const float* src = g_w4 + (ch + 2) * CCH;
            uint32_t dst = smb + (CB_F + (ch % 2) * CCH) * 4;
            for (int i = tid; i < CCH / 4; i += NTHR)
                cp16(dst + i * 16, src + i * 4);
            cp_commit();
        }
    }

    // write end
    float* outb = out + b * NC_ * T_LEN;
    const int t = t0 + (tg << 2);
#pragma unroll
    for (int p = 0; p < 4; p++) {
        float2 v0 = unpack2(acc2[p][0]);
        float2 v1 = unpack2(acc2[p][1]);
        float2 v2 = unpack2(acc2[p][2]);
        float2 v3 = unpack2(acc2[p][3]);
        int o = og * 8 + p * 2;
        *(float4*)(outb + (o << 15) + t) = make_float4(v0.x, v1.x, v2.x, v3.x);
        *(float4*)(outb + ((o + 1) << 15) + t) = make_float4(v0.y, v1.y, v2.y, v3.y);
    }
}

// ---------------------------------------------------------------------------
extern "C" void kernel_launch(void* const* d_in, const int* in_sizes, int n_in,
                              void* d_out, int out_size) {
    const float* wav    = (const float*)d_in[0];
    const float* cond   = (const float*)d_in[1];
    const float* wav_w  = (const float*)d_in[2];
    const float* wav_b  = (const float*)d_in[3];
    const float* cond_w = (const float*)d_in[4];
    const float* cond_b = (const float*)d_in[5];
    const float* dil_w  = (const float*)d_in[6];
    const float* dil_b  = (const float*)d_in[7];
    const float* skip_w = (const float*)d_in[8];
    const float* skip_b = (const float*)d_in[9];
    const float* res_w  = (const float*)d_in[10];
    const float* res_b  = (const float*)d_in[11];
    const float* out_w  = (const float*)d_in[12];
    const float* out_b  = (const float*)d_in[13];
    const float* end_w  = (const float*)d_in[14];
    const float* end_b  = (const float*)d_in[15];
    float* out = (float*)d_out;

    const int SMEM_BLK = 50880 * (int)sizeof(float);   // 203520
    const int SMEM_FIN = 52224 * (int)sizeof(float);   // 208896
    cudaFuncSetAttribute(block_kernel, cudaFuncAttributeMaxDynamicSharedMemorySize, SMEM_BLK);
    cudaFuncSetAttribute(final_kernel, cudaFuncAttributeMaxDynamicSharedMemorySize, SMEM_FIN);

    prep_kernel<<<512, 256>>>(cond_w, dil_w, skip_w, res_w, out_w, end_w);
    init_kernel<<<592, 256>>>(wav, wav_w, wav_b);

    dim3 grid(T_LEN / TT_, BN);
    for (int i = 0; i < NB_; i++) {
        int d = 1 << (i & 7);
        block_kernel<<<grid, NTHR, SMEM_BLK>>>(i, d, i & 1, cond,
                                               dil_b, cond_b, skip_b, res_b);
    }
    final_kernel<<<grid, NTHR, SMEM_FIN>>>(out, out_b, end_b);
}